// round 9
// baseline (speedup 1.0000x reference)
#include <cuda_runtime.h>

#define Bb 2
#define Ss 2048
#define Dd 512
#define Hh 8
#define DHh 64
#define CAPS 128     // candidate cap per row (final-threshold counts ~5-25)

// Scratch (device globals: no runtime allocation allowed)
__device__ float          g_Q[Bb * Hh * Ss * DHh];       // [B,H,S,dh]  8 MB
__device__ float          g_K[Bb * Hh * Ss * DHh];       // [B,H,S,dh]  8 MB
__device__ float          g_V[Bb * Ss * DHh];            // [B,S,dh]    1 MB
__device__ float          g_heads[Bb * Ss * Dd];         // [B,S,D]     8 MB
__device__ unsigned short g_cand[Bb * Hh * Ss * CAPS];   // cand indices
__device__ int            g_ccnt[Bb * Hh * Ss];          // cand counts
__device__ float          g_rmax[Bb * Hh * Ss];          // tf32 row maxes

// monotone float<->unsigned encoding for atomicMax on floats
__device__ __forceinline__ unsigned enc_f(float f) {
    unsigned b = __float_as_uint(f);
    return (f >= 0.0f) ? (b | 0x80000000u) : ~b;
}
__device__ __forceinline__ float dec_f(unsigned u) {
    return (u & 0x80000000u) ? __uint_as_float(u & 0x7fffffffu)
                             : __uint_as_float(~u);
}

// ---------------------------------------------------------------------------
// Fused Q/K/V projection: one launch, grid (32, 17).
//   y in [0,8)  : Q n-block y      -> g_Q   [B,H,S,dh] head-major
//   y in [8,16) : K n-block y-8    -> g_K   [B,H,S,dh] head-major
//   y == 16     : V (64 cols)      -> g_V   [B,S,dh]
// Tile 128x64, BK=16, 256 threads, 8x4 per thread.
// ---------------------------------------------------------------------------
__global__ __launch_bounds__(256) void proj_qkv(
    const float* __restrict__ x,
    const float* __restrict__ Wq, const float* __restrict__ bq,
    const float* __restrict__ Wk, const float* __restrict__ bk,
    const float* __restrict__ Wv, const float* __restrict__ bv,
    float* __restrict__ Qo, float* __restrict__ Ko, float* __restrict__ Vo)
{
    const int BK = 16;
    __shared__ float As[BK][128 + 4];
    __shared__ float Bs[BK][64 + 4];

    int y = blockIdx.y;
    const float* W; const float* bias; float* C;
    int n0, ldb, headMajor;
    if (y < 8)       { W = Wq; bias = bq; C = Qo; n0 = y * 64;        ldb = Dd;  headMajor = 1; }
    else if (y < 16) { W = Wk; bias = bk; C = Ko; n0 = (y - 8) * 64;  ldb = Dd;  headMajor = 1; }
    else             { W = Wv; bias = bv; C = Vo; n0 = 0;             ldb = DHh; headMajor = 0; }

    int tid = threadIdx.x;
    int tx = tid & 15;
    int ty = tid >> 4;
    int m0 = blockIdx.x * 128;

    int ar = tid >> 1;
    int ac = (tid & 1) * 8;
    int br_k = tid >> 4;
    int bc_n = (tid & 15) * 4;

    float acc[8][4];
#pragma unroll
    for (int i = 0; i < 8; ++i)
#pragma unroll
        for (int j = 0; j < 4; ++j) acc[i][j] = 0.0f;

    for (int k0 = 0; k0 < Dd; k0 += BK) {
        {
            const float* ap = x + (long)(m0 + ar) * Dd + k0 + ac;
            float4 v0 = *(const float4*)(ap);
            float4 v1 = *(const float4*)(ap + 4);
            As[ac + 0][ar] = v0.x; As[ac + 1][ar] = v0.y;
            As[ac + 2][ar] = v0.z; As[ac + 3][ar] = v0.w;
            As[ac + 4][ar] = v1.x; As[ac + 5][ar] = v1.y;
            As[ac + 6][ar] = v1.z; As[ac + 7][ar] = v1.w;
        }
        {
            float4 v = *(const float4*)(W + (long)(k0 + br_k) * ldb + n0 + bc_n);
            *(float4*)&Bs[br_k][bc_n] = v;
        }
        __syncthreads();

#pragma unroll
        for (int k = 0; k < BK; ++k) {
            float a[8], b[4];
            *(float4*)&a[0] = *(const float4*)&As[k][ty * 8];
            *(float4*)&a[4] = *(const float4*)&As[k][ty * 8 + 4];
            *(float4*)&b[0] = *(const float4*)&Bs[k][tx * 4];
#pragma unroll
            for (int i = 0; i < 8; ++i)
#pragma unroll
                for (int j = 0; j < 4; ++j)
                    acc[i][j] += a[i] * b[j];
        }
        __syncthreads();
    }

    float4 bv4 = *(const float4*)(bias + n0 + tx * 4);

#pragma unroll
    for (int i = 0; i < 8; ++i) {
        int m = m0 + ty * 8 + i;
        float4 o;
        o.x = acc[i][0] + bv4.x;
        o.y = acc[i][1] + bv4.y;
        o.z = acc[i][2] + bv4.z;
        o.w = acc[i][3] + bv4.w;
        long addr;
        if (headMajor) {
            int bb = m >> 11;
            int ss = m & 2047;
            int hh = n0 >> 6;
            addr = ((((long)bb * Hh + hh) * Ss) + ss) * DHh + tx * 4;
        } else {
            addr = (long)m * DHh + tx * 4;
        }
        *(float4*)(C + addr) = o;
    }
}

// ---------------------------------------------------------------------------
// fp32 SGEMM (output proj): C = A (MxK) * B (KxN) + bias
// ---------------------------------------------------------------------------
__global__ __launch_bounds__(256) void sgemm_128x64(
    const float* __restrict__ A, int lda,
    const float* __restrict__ Bmat, int ldb,
    const float* __restrict__ bias,
    float* __restrict__ C, int ldc, int Kdim)
{
    const int BK = 16;
    __shared__ float As[BK][128 + 4];
    __shared__ float Bs[BK][64 + 4];

    int tid = threadIdx.x;
    int tx = tid & 15;
    int ty = tid >> 4;
    int m0 = blockIdx.x * 128;
    int n0 = blockIdx.y * 64;

    int ar = tid >> 1;
    int ac = (tid & 1) * 8;
    int br_k = tid >> 4;
    int bc_n = (tid & 15) * 4;

    float acc[8][4];
#pragma unroll
    for (int i = 0; i < 8; ++i)
#pragma unroll
        for (int j = 0; j < 4; ++j) acc[i][j] = 0.0f;

    for (int k0 = 0; k0 < Kdim; k0 += BK) {
        {
            const float* ap = A + (long)(m0 + ar) * lda + k0 + ac;
            float4 v0 = *(const float4*)(ap);
            float4 v1 = *(const float4*)(ap + 4);
            As[ac + 0][ar] = v0.x; As[ac + 1][ar] = v0.y;
            As[ac + 2][ar] = v0.z; As[ac + 3][ar] = v0.w;
            As[ac + 4][ar] = v1.x; As[ac + 5][ar] = v1.y;
            As[ac + 6][ar] = v1.z; As[ac + 7][ar] = v1.w;
        }
        {
            float4 v = *(const float4*)(Bmat + (long)(k0 + br_k) * ldb + n0 + bc_n);
            *(float4*)&Bs[br_k][bc_n] = v;
        }
        __syncthreads();

#pragma unroll
        for (int k = 0; k < BK; ++k) {
            float a[8], b[4];
            *(float4*)&a[0] = *(const float4*)&As[k][ty * 8];
            *(float4*)&a[4] = *(const float4*)&As[k][ty * 8 + 4];
            *(float4*)&b[0] = *(const float4*)&Bs[k][tx * 4];
#pragma unroll
            for (int i = 0; i < 8; ++i)
#pragma unroll
                for (int j = 0; j < 4; ++j)
                    acc[i][j] += a[i] * b[j];
        }
        __syncthreads();
    }

    float4 bv = *(const float4*)(bias + n0 + tx * 4);

#pragma unroll
    for (int i = 0; i < 8; ++i) {
        int m = m0 + ty * 8 + i;
        float4 o;
        o.x = acc[i][0] + bv.x;
        o.y = acc[i][1] + bv.y;
        o.z = acc[i][2] + bv.z;
        o.w = acc[i][3] + bv.w;
        *(float4*)(C + (long)m * ldc + n0 + tx * 4) = o;
    }
}

// ---------------------------------------------------------------------------
// Fused QK + TWO-PASS screening (final-threshold; no logits materialization).
// Pass A: mma all 16 K-tiles, reduce exact per-row maxima (shared atomicMax).
// Pass B: mma again, screen {z > rowmax_final - 1.02} into per-row u16 lists
// with a deterministic quad-prefix append (phase wn=0 then wn=1).
// Superset proof: support z > tau >= zmax-1; 0.02 margin >> tf32 error.
// ---------------------------------------------------------------------------
__device__ __forceinline__ unsigned f2tf32(float f) {
    unsigned u;
    asm("cvt.rna.tf32.f32 %0, %1;" : "=r"(u) : "f"(f));
    return u;
}

#define QK_LDS 68
#define SCR_SMEM (2 * 128 * QK_LDS * 4 + 128 * CAPS * 2 + 128 * 4 + 128 * 4 + 128 * 4)

__device__ __forceinline__ void tile_mma(
    const unsigned* Qs, const unsigned* Ks,
    int wm, int wn, int g, int tg, float acc[2][8][4])
{
#pragma unroll
    for (int mt = 0; mt < 2; ++mt)
#pragma unroll
        for (int nt = 0; nt < 8; ++nt)
#pragma unroll
            for (int e = 0; e < 4; ++e) acc[mt][nt][e] = 0.0f;

#pragma unroll
    for (int ks = 0; ks < 8; ++ks) {
        int kc = ks * 8;
        unsigned a[2][4];
#pragma unroll
        for (int mt = 0; mt < 2; ++mt) {
            int r = wm * 32 + mt * 16 + g;
            a[mt][0] = Qs[(r) * QK_LDS + kc + tg];
            a[mt][1] = Qs[(r + 8) * QK_LDS + kc + tg];
            a[mt][2] = Qs[(r) * QK_LDS + kc + tg + 4];
            a[mt][3] = Qs[(r + 8) * QK_LDS + kc + tg + 4];
        }
        unsigned b[8][2];
#pragma unroll
        for (int nt = 0; nt < 8; ++nt) {
            int n = wn * 64 + nt * 8 + g;
            b[nt][0] = Ks[n * QK_LDS + kc + tg];
            b[nt][1] = Ks[n * QK_LDS + kc + tg + 4];
        }
#pragma unroll
        for (int mt = 0; mt < 2; ++mt)
#pragma unroll
            for (int nt = 0; nt < 8; ++nt) {
                asm volatile(
                    "mma.sync.aligned.m16n8k8.row.col.f32.tf32.tf32.f32 "
                    "{%0,%1,%2,%3}, {%4,%5,%6,%7}, {%8,%9}, {%0,%1,%2,%3};"
                    : "+f"(acc[mt][nt][0]), "+f"(acc[mt][nt][1]),
                      "+f"(acc[mt][nt][2]), "+f"(acc[mt][nt][3])
                    : "r"(a[mt][0]), "r"(a[mt][1]), "r"(a[mt][2]), "r"(a[mt][3]),
                      "r"(b[nt][0]), "r"(b[nt][1]));
            }
    }
}

__global__ __launch_bounds__(256) void qk_screen(
    const float* __restrict__ Q, const float* __restrict__ K,
    unsigned short* __restrict__ cand, int* __restrict__ ccnt,
    float* __restrict__ rmaxf)
{
    extern __shared__ unsigned sm[];
    unsigned* Qs = sm;                                   // [128][68]
    unsigned* Ks = sm + 128 * QK_LDS;                    // [128][68]
    unsigned short* jl = (unsigned short*)(sm + 2 * 128 * QK_LDS); // [128][CAPS]
    unsigned* rmaxs = (unsigned*)(jl + 128 * CAPS);      // [128] encoded
    float* thrs = (float*)(rmaxs + 128);                 // [128] final thr
    int* cnts = (int*)(thrs + 128);                      // [128]

    int tid = threadIdx.x;
    int wid = tid >> 5, lane = tid & 31;
    int wm = wid & 3;
    int wn = wid >> 2;
    int g = lane >> 2;
    int tg = lane & 3;
    int qb = lane & ~3;

    int bh = blockIdx.z;
    int q0 = blockIdx.x * 128;

    for (int r = tid; r < 128; r += 256) { rmaxs[r] = 0u; cnts[r] = 0; }

    // stage Q tile once
    const float* Qg = Q + ((long)bh * Ss + q0) * DHh;
#pragma unroll
    for (int p = 0; p < 8; ++p) {
        int r = (tid >> 4) + p * 16;
        int c = (tid & 15) * 4;
        float4 v = *(const float4*)(Qg + r * DHh + c);
        unsigned* q = Qs + r * QK_LDS + c;
        q[0] = f2tf32(v.x); q[1] = f2tf32(v.y);
        q[2] = f2tf32(v.z); q[3] = f2tf32(v.w);
    }
    __syncthreads();

    float acc[2][8][4];

    // ---------------- pass A: row maxima ----------------
    for (int t = 0; t < 16; ++t) {
        const float* Kg = K + ((long)bh * Ss + t * 128) * DHh;
#pragma unroll
        for (int p = 0; p < 8; ++p) {
            int r = (tid >> 4) + p * 16;
            int c = (tid & 15) * 4;
            float4 v = *(const float4*)(Kg + r * DHh + c);
            unsigned* kk = Ks + r * QK_LDS + c;
            kk[0] = f2tf32(v.x); kk[1] = f2tf32(v.y);
            kk[2] = f2tf32(v.z); kk[3] = f2tf32(v.w);
        }
        __syncthreads();

        tile_mma(Qs, Ks, wm, wn, g, tg, acc);

#pragma unroll
        for (int mt = 0; mt < 2; ++mt) {
            float m0 = -3e38f, m1 = -3e38f;
#pragma unroll
            for (int nt = 0; nt < 8; ++nt) {
                m0 = fmaxf(m0, fmaxf(acc[mt][nt][0], acc[mt][nt][1]));
                m1 = fmaxf(m1, fmaxf(acc[mt][nt][2], acc[mt][nt][3]));
            }
#pragma unroll
            for (int off = 1; off <= 2; off <<= 1) {
                m0 = fmaxf(m0, __shfl_xor_sync(0xffffffffu, m0, off));
                m1 = fmaxf(m1, __shfl_xor_sync(0xffffffffu, m1, off));
            }
            if (tg == 0) {
                atomicMax(&rmaxs[wm * 32 + mt * 16 + g], enc_f(m0));
                atomicMax(&rmaxs[wm * 32 + mt * 16 + g + 8], enc_f(m1));
            }
        }
        __syncthreads();
    }

    // finalize thresholds
    for (int r = tid; r < 128; r += 256) thrs[r] = dec_f(rmaxs[r]) - 1.02f;
    __syncthreads();

    // ---------------- pass B: screen vs final threshold ----------------
    for (int t = 0; t < 16; ++t) {
        const float* Kg = K + ((long)bh * Ss + t * 128) * DHh;
#pragma unroll
        for (int p = 0; p < 8; ++p) {
            int r = (tid >> 4) + p * 16;
            int c = (tid & 15) * 4;
            float4 v = *(const float4*)(Kg + r * DHh + c);
            unsigned* kk = Ks + r * QK_LDS + c;
            kk[0] = f2tf32(v.x); kk[1] = f2tf32(v.y);
            kk[2] = f2tf32(v.z); kk[3] = f2tf32(v.w);
        }
        __syncthreads();

        tile_mma(Qs, Ks, wm, wn, g, tg, acc);

        // deterministic append: wn=0 first, then wn=1
        for (int phase = 0; phase < 2; ++phase) {
            if (wn == phase) {
#pragma unroll
                for (int mt = 0; mt < 2; ++mt) {
#pragma unroll
                    for (int half = 0; half < 2; ++half) {
                        int r = wm * 32 + mt * 16 + g + half * 8;
                        float thr = thrs[r];
                        unsigned m = 0;
#pragma unroll
                        for (int nt = 0; nt < 8; ++nt) {
#pragma unroll
                            for (int ee = 0; ee < 2; ++ee)
                                if (acc[mt][nt][half * 2 + ee] > thr)
                                    m |= 1u << (nt * 2 + ee);
                        }
                        int c = __popc(m);
                        int c0 = __shfl_sync(0xffffffffu, c, qb);
                        int c1 = __shfl_sync(0xffffffffu, c, qb + 1);
                        int c2 = __shfl_sync(0xffffffffu, c, qb + 2);
                        int c3 = __shfl_sync(0xffffffffu, c, qb + 3);
                        int pre = (tg > 0 ? c0 : 0) + (tg > 1 ? c1 : 0) + (tg > 2 ? c2 : 0);
                        int tot = c0 + c1 + c2 + c3;
                        int base = cnts[r];
                        int pos = base + pre;
                        while (m) {
                            int bit = __ffs(m) - 1; m &= m - 1;
                            int j = t * 128 + wn * 64 + (bit >> 1) * 8 + tg * 2 + (bit & 1);
                            if (pos < CAPS) jl[r * CAPS + pos] = (unsigned short)j;
                            ++pos;
                        }
                        __syncwarp();
                        if (tg == 0) cnts[r] = base + tot;
                        __syncwarp();
                    }
                }
            }
            __syncthreads();
        }
    }

    // write results
    long rowg0 = (long)bh * Ss + q0;
    for (int r = tid; r < 128; r += 256) {
        ccnt[rowg0 + r] = cnts[r];
        rmaxf[rowg0 + r] = dec_f(rmaxs[r]);
    }
    __syncthreads();
    for (int r = wid; r < 128; r += 8) {
        int c = min(cnts[r], CAPS);
        unsigned short* dst = cand + (rowg0 + r) * CAPS;
        for (int e = lane; e < c; e += 32) dst[e] = jl[r * CAPS + e];
    }
}

// ---------------------------------------------------------------------------
// Finish: exact fp32 candidate logits, Michelot tau, heads, avg.
// Warp w = head w of row (b,i). Overflow (practically unreachable with the
// final-threshold screen) -> exact dense warp-cooperative path.
// ---------------------------------------------------------------------------
__global__ __launch_bounds__(256) void sparse_final(
    const unsigned short* __restrict__ cand, const int* __restrict__ ccnt,
    const float* __restrict__ rmaxf,
    const float* __restrict__ Q, const float* __restrict__ K,
    const float* __restrict__ V,
    float* __restrict__ heads, float* __restrict__ avg_out)
{
    __shared__ float s_z[Hh][CAPS];
    __shared__ short s_j[Hh][CAPS];
    __shared__ float s_tau[Hh];
    __shared__ int   s_cnt[Hh];
    __shared__ float s_avg[Ss];

    int row = blockIdx.x;
    int b = row >> 11;
    int i = row & 2047;
    int tid = threadIdx.x;
    int w = tid >> 5;
    int lane = tid & 31;

    for (int j = tid; j < Ss; j += 256) s_avg[j] = 0.0f;
    __syncthreads();

    long bhrow = ((long)b * Hh + w) * Ss + i;
    const float* Qrow = Q + bhrow * DHh;
    const float* Kbh  = K + (((long)b * Hh + w) * Ss) * (long)DHh;
    const float* Vb   = V + (long)b * Ss * DHh;
    float q0 = Qrow[lane], q1 = Qrow[lane + 32];

    int n = ccnt[bhrow];
    float o0 = 0.0f, o1 = 0.0f;

    if (n <= CAPS) {
        // normal path: load candidates, exact fp32 recompute (2-way ILP)
        const unsigned short* cr = cand + bhrow * CAPS;
        for (int e = lane; e < n; e += 32) s_j[w][e] = (short)cr[e];
        __syncwarp();

        int e = 0;
        for (; e + 2 <= n; e += 2) {
            int j0 = s_j[w][e], j1 = s_j[w][e + 1];
            const float* K0 = Kbh + (long)j0 * DHh;
            const float* K1 = Kbh + (long)j1 * DHh;
            float p0 = q0 * K0[lane] + q1 * K0[lane + 32];
            float p1 = q0 * K1[lane] + q1 * K1[lane + 32];
#pragma unroll
            for (int off = 16; off; off >>= 1) {
                p0 += __shfl_xor_sync(0xffffffffu, p0, off);
                p1 += __shfl_xor_sync(0xffffffffu, p1, off);
            }
            if (lane == 0) { s_z[w][e] = p0; s_z[w][e + 1] = p1; }
        }
        if (e < n) {
            int j0 = s_j[w][e];
            const float* K0 = Kbh + (long)j0 * DHh;
            float p0 = q0 * K0[lane] + q1 * K0[lane + 32];
#pragma unroll
            for (int off = 16; off; off >>= 1)
                p0 += __shfl_xor_sync(0xffffffffu, p0, off);
            if (lane == 0) s_z[w][e] = p0;
        }
        __syncwarp();

        // exact tau: Michelot over candidate superset
        float tau = rmaxf[bhrow] - 1.02f;
        for (int it = 0; it < 48; ++it) {
            float s = 0.0f; int c = 0;
            for (int e2 = lane; e2 < n; e2 += 32) {
                float zz = s_z[w][e2];
                if (zz > tau) { s += zz; c++; }
            }
#pragma unroll
            for (int off = 16; off; off >>= 1) {
                s += __shfl_xor_sync(0xffffffffu, s, off);
                c += __shfl_xor_sync(0xffffffffu, c, off);
            }
            float nt2 = (s - 1.0f) / (float)c;
            if (nt2 == tau) break;
            tau = nt2;
        }
        if (lane == 0) { s_tau[w] = tau; s_cnt[w] = n; }

        // heads from sparse support
        for (int e2 = 0; e2 < n; ++e2) {
            float p = s_z[w][e2] - tau;
            if (p > 0.0f) {
                const float* Vr = Vb + (long)s_j[w][e2] * DHh;
                o0 += p * Vr[lane];
                o1 += p * Vr[lane + 32];
            }
        }
    } else {
        // overflow (unreachable): exact dense, coalesced, deterministic
        // (every lane accumulates identical totals -> no reduce needed)
        float tau = rmaxf[bhrow] - 1.02f;
        for (int it = 0; it < 48; ++it) {
            float s = 0.0f; int c = 0;
            for (int j0 = 0; j0 < Ss; j0 += 4) {
                float p[4];
#pragma unroll
                for (int u = 0; u < 4; ++u) {
                    const float* Kr = Kbh + (long)(j0 + u) * DHh;
                    p[u] = q0 * Kr[lane] + q1 * Kr[lane + 32];
                }
#pragma unroll
                for (int off = 16; off; off >>= 1)
#pragma unroll
                    for (int u = 0; u < 4; ++u)
                        p[u] += __shfl_xor_sync(0xffffffffu, p[u], off);
#pragma unroll
                for (int u = 0; u < 4; ++u)
                    if (p[u] > tau) { s += p[u]; c++; }
            }
            float nt2 = (s - 1.0f) / (float)c;
            if (nt2 == tau) break;
            tau = nt2;
        }
        for (int j0 = 0; j0 < Ss; j0 += 4) {
            float p[4];
#pragma unroll
            for (int u = 0; u < 4; ++u) {
                const float* Kr = Kbh + (long)(j0 + u) * DHh;
                p[u] = q0 * Kr[lane] + q1 * Kr[lane + 32];
            }
#pragma unroll
            for (int off = 16; off; off >>= 1)
#pragma unroll
                for (int u = 0; u < 4; ++u)
                    p[u] += __shfl_xor_sync(0xffffffffu, p[u], off);
#pragma unroll
            for (int u = 0; u < 4; ++u) {
                float pv = p[u] - tau;
                if (pv > 0.0f) {
                    o0 += pv * Vb[(long)(j0 + u) * DHh + lane];
                    o1 += pv * Vb[(long)(j0 + u) * DHh + lane + 32];
                    if (lane == 0) atomicAdd(&s_avg[j0 + u], pv);
                }
            }
        }
        if (lane == 0) { s_tau[w] = tau; s_cnt[w] = 0; }
    }

    long hbase = (long)row * Dd + w * DHh;
    heads[hbase + lane] = o0;
    heads[hbase + lane + 32] = o1;

    __syncthreads();

    // avg_attention: deterministic ownership scan over candidate lists
    float rv[8];
#pragma unroll
    for (int k = 0; k < 8; ++k) rv[k] = s_avg[tid + k * 256];
#pragma unroll
    for (int h = 0; h < Hh; ++h) {
        int c = s_cnt[h];
        float th = s_tau[h];
        for (int e = 0; e < c; ++e) {
            int j = s_j[h][e];
            if ((j & 255) == tid) {
                float p = s_z[h][e] - th;
                if (p > 0.0f) rv[j >> 8] += p;
            }
        }
    }
    long abase = ((long)b * Ss + i) * (long)Ss;
#pragma unroll
    for (int k = 0; k < 8; ++k)
        avg_out[abase + tid + k * 256] = 0.125f * rv[k];
}

// ---------------------------------------------------------------------------
extern "C" void kernel_launch(void* const* d_in, const int* in_sizes, int n_in,
                              void* d_out, int out_size)
{
    const float* x    = (const float*)d_in[0];
    const float* Wq   = (const float*)d_in[1];
    const float* bq   = (const float*)d_in[2];
    const float* Wk   = (const float*)d_in[3];
    const float* bk   = (const float*)d_in[4];
    const float* Wv   = (const float*)d_in[5];
    const float* bv   = (const float*)d_in[6];
    const float* Wout = (const float*)d_in[7];
    const float* bout = (const float*)d_in[8];

    float* out   = (float*)d_out;
    float* x_out = out;                              // [B,S,D]
    float* avg   = out + (long)Bb * Ss * Dd;         // [B,S,S]

    float *Qp, *Kp, *Vp, *Hp, *Rp;
    unsigned short* Cp;
    int* Np;
    cudaGetSymbolAddress((void**)&Qp, g_Q);
    cudaGetSymbolAddress((void**)&Kp, g_K);
    cudaGetSymbolAddress((void**)&Vp, g_V);
    cudaGetSymbolAddress((void**)&Hp, g_heads);
    cudaGetSymbolAddress((void**)&Cp, g_cand);
    cudaGetSymbolAddress((void**)&Np, g_ccnt);
    cudaGetSymbolAddress((void**)&Rp, g_rmax);

    cudaFuncSetAttribute(qk_screen,
                         cudaFuncAttributeMaxDynamicSharedMemorySize,
                         SCR_SMEM);

    // fused Q/K/V projections (one launch)
    proj_qkv<<<dim3(32, 17, 1), 256>>>(x, Wq, bq, Wk, bk, Wv, bv, Qp, Kp, Vp);

    // fused QK + two-pass candidate screening (final threshold)
    qk_screen<<<dim3(Ss / 128, 1, Bb * Hh), 256, SCR_SMEM>>>(
        Qp, Kp, Cp, Np, Rp);

    // exact sparsemax + heads + avg from candidate lists
    sparse_final<<<Bb * Ss, 256>>>(Cp, Np, Rp, Qp, Kp, Vp, Hp, avg);

    // x_out = heads @ Wout + bout
    sgemm_128x64<<<dim3(32, 8, 1), 256>>>(Hp, Dd, Wout, Dd, bout, x_out, Dd, Dd);
}

// round 10
// speedup vs baseline: 2.8845x; 2.8845x over previous
#include <cuda_runtime.h>

#define Bb 2
#define Ss 2048
#define Dd 512
#define Hh 8
#define DHh 64
#define CAPS 128     // candidate cap per row

// Scratch (device globals: no runtime allocation allowed)
__device__ float          g_Q[Bb * Hh * Ss * DHh];       // [B,H,S,dh]  8 MB
__device__ float          g_K[Bb * Hh * Ss * DHh];       // [B,H,S,dh]  8 MB
__device__ float          g_V[Bb * Ss * DHh];            // [B,S,dh]    1 MB
__device__ float          g_heads[Bb * Ss * Dd];         // [B,S,D]     8 MB
__device__ unsigned short g_cand[Bb * Hh * Ss * CAPS];   // cand indices
__device__ int            g_ccnt[Bb * Hh * Ss];          // cand counts
__device__ float          g_rmax[Bb * Hh * Ss];          // tf32 row maxes

__device__ __forceinline__ unsigned enc_f(float f) {
    unsigned b = __float_as_uint(f);
    return (f >= 0.0f) ? (b | 0x80000000u) : ~b;
}
__device__ __forceinline__ float dec_f(unsigned u) {
    return (u & 0x80000000u) ? __uint_as_float(u & 0x7fffffffu)
                             : __uint_as_float(~u);
}

// ---------------------------------------------------------------------------
// Fused Q/K/V projection: one launch, grid (32, 17).
// ---------------------------------------------------------------------------
__global__ __launch_bounds__(256) void proj_qkv(
    const float* __restrict__ x,
    const float* __restrict__ Wq, const float* __restrict__ bq,
    const float* __restrict__ Wk, const float* __restrict__ bk,
    const float* __restrict__ Wv, const float* __restrict__ bv,
    float* __restrict__ Qo, float* __restrict__ Ko, float* __restrict__ Vo)
{
    const int BK = 16;
    __shared__ float As[BK][128 + 4];
    __shared__ float Bs[BK][64 + 4];

    int y = blockIdx.y;
    const float* W; const float* bias; float* C;
    int n0, ldb, headMajor;
    if (y < 8)       { W = Wq; bias = bq; C = Qo; n0 = y * 64;        ldb = Dd;  headMajor = 1; }
    else if (y < 16) { W = Wk; bias = bk; C = Ko; n0 = (y - 8) * 64;  ldb = Dd;  headMajor = 1; }
    else             { W = Wv; bias = bv; C = Vo; n0 = 0;             ldb = DHh; headMajor = 0; }

    int tid = threadIdx.x;
    int tx = tid & 15;
    int ty = tid >> 4;
    int m0 = blockIdx.x * 128;

    int ar = tid >> 1;
    int ac = (tid & 1) * 8;
    int br_k = tid >> 4;
    int bc_n = (tid & 15) * 4;

    float acc[8][4];
#pragma unroll
    for (int i = 0; i < 8; ++i)
#pragma unroll
        for (int j = 0; j < 4; ++j) acc[i][j] = 0.0f;

    for (int k0 = 0; k0 < Dd; k0 += BK) {
        {
            const float* ap = x + (long)(m0 + ar) * Dd + k0 + ac;
            float4 v0 = *(const float4*)(ap);
            float4 v1 = *(const float4*)(ap + 4);
            As[ac + 0][ar] = v0.x; As[ac + 1][ar] = v0.y;
            As[ac + 2][ar] = v0.z; As[ac + 3][ar] = v0.w;
            As[ac + 4][ar] = v1.x; As[ac + 5][ar] = v1.y;
            As[ac + 6][ar] = v1.z; As[ac + 7][ar] = v1.w;
        }
        {
            float4 v = *(const float4*)(W + (long)(k0 + br_k) * ldb + n0 + bc_n);
            *(float4*)&Bs[br_k][bc_n] = v;
        }
        __syncthreads();

#pragma unroll
        for (int k = 0; k < BK; ++k) {
            float a[8], b[4];
            *(float4*)&a[0] = *(const float4*)&As[k][ty * 8];
            *(float4*)&a[4] = *(const float4*)&As[k][ty * 8 + 4];
            *(float4*)&b[0] = *(const float4*)&Bs[k][tx * 4];
#pragma unroll
            for (int i = 0; i < 8; ++i)
#pragma unroll
                for (int j = 0; j < 4; ++j)
                    acc[i][j] += a[i] * b[j];
        }
        __syncthreads();
    }

    float4 bv4 = *(const float4*)(bias + n0 + tx * 4);

#pragma unroll
    for (int i = 0; i < 8; ++i) {
        int m = m0 + ty * 8 + i;
        float4 o;
        o.x = acc[i][0] + bv4.x;
        o.y = acc[i][1] + bv4.y;
        o.z = acc[i][2] + bv4.z;
        o.w = acc[i][3] + bv4.w;
        long addr;
        if (headMajor) {
            int bb = m >> 11;
            int ss = m & 2047;
            int hh = n0 >> 6;
            addr = ((((long)bb * Hh + hh) * Ss) + ss) * DHh + tx * 4;
        } else {
            addr = (long)m * DHh + tx * 4;
        }
        *(float4*)(C + addr) = o;
    }
}

// ---------------------------------------------------------------------------
// fp32 SGEMM (output proj): C = A (MxK) * B (KxN) + bias
// ---------------------------------------------------------------------------
__global__ __launch_bounds__(256) void sgemm_128x64(
    const float* __restrict__ A, int lda,
    const float* __restrict__ Bmat, int ldb,
    const float* __restrict__ bias,
    float* __restrict__ C, int ldc, int Kdim)
{
    const int BK = 16;
    __shared__ float As[BK][128 + 4];
    __shared__ float Bs[BK][64 + 4];

    int tid = threadIdx.x;
    int tx = tid & 15;
    int ty = tid >> 4;
    int m0 = blockIdx.x * 128;
    int n0 = blockIdx.y * 64;

    int ar = tid >> 1;
    int ac = (tid & 1) * 8;
    int br_k = tid >> 4;
    int bc_n = (tid & 15) * 4;

    float acc[8][4];
#pragma unroll
    for (int i = 0; i < 8; ++i)
#pragma unroll
        for (int j = 0; j < 4; ++j) acc[i][j] = 0.0f;

    for (int k0 = 0; k0 < Kdim; k0 += BK) {
        {
            const float* ap = A + (long)(m0 + ar) * lda + k0 + ac;
            float4 v0 = *(const float4*)(ap);
            float4 v1 = *(const float4*)(ap + 4);
            As[ac + 0][ar] = v0.x; As[ac + 1][ar] = v0.y;
            As[ac + 2][ar] = v0.z; As[ac + 3][ar] = v0.w;
            As[ac + 4][ar] = v1.x; As[ac + 5][ar] = v1.y;
            As[ac + 6][ar] = v1.z; As[ac + 7][ar] = v1.w;
        }
        {
            float4 v = *(const float4*)(Bmat + (long)(k0 + br_k) * ldb + n0 + bc_n);
            *(float4*)&Bs[br_k][bc_n] = v;
        }
        __syncthreads();

#pragma unroll
        for (int k = 0; k < BK; ++k) {
            float a[8], b[4];
            *(float4*)&a[0] = *(const float4*)&As[k][ty * 8];
            *(float4*)&a[4] = *(const float4*)&As[k][ty * 8 + 4];
            *(float4*)&b[0] = *(const float4*)&Bs[k][tx * 4];
#pragma unroll
            for (int i = 0; i < 8; ++i)
#pragma unroll
                for (int j = 0; j < 4; ++j)
                    acc[i][j] += a[i] * b[j];
        }
        __syncthreads();
    }

    float4 bv = *(const float4*)(bias + n0 + tx * 4);

#pragma unroll
    for (int i = 0; i < 8; ++i) {
        int m = m0 + ty * 8 + i;
        float4 o;
        o.x = acc[i][0] + bv.x;
        o.y = acc[i][1] + bv.y;
        o.z = acc[i][2] + bv.z;
        o.w = acc[i][3] + bv.w;
        *(float4*)(C + (long)m * ldc + n0 + tx * 4) = o;
    }
}

// ---------------------------------------------------------------------------
// Fused QK + TWO-PASS screening (final threshold; no logits materialization).
// ---------------------------------------------------------------------------
__device__ __forceinline__ unsigned f2tf32(float f) {
    unsigned u;
    asm("cvt.rna.tf32.f32 %0, %1;" : "=r"(u) : "f"(f));
    return u;
}

#define QK_LDS 68
#define SCR_SMEM (2 * 128 * QK_LDS * 4 + 128 * CAPS * 2 + 128 * 4 + 128 * 4 + 128 * 4)

__device__ __forceinline__ void tile_mma(
    const unsigned* Qs, const unsigned* Ks,
    int wm, int wn, int g, int tg, float acc[2][8][4])
{
#pragma unroll
    for (int mt = 0; mt < 2; ++mt)
#pragma unroll
        for (int nt = 0; nt < 8; ++nt)
#pragma unroll
            for (int e = 0; e < 4; ++e) acc[mt][nt][e] = 0.0f;

#pragma unroll
    for (int ks = 0; ks < 8; ++ks) {
        int kc = ks * 8;
        unsigned a[2][4];
#pragma unroll
        for (int mt = 0; mt < 2; ++mt) {
            int r = wm * 32 + mt * 16 + g;
            a[mt][0] = Qs[(r) * QK_LDS + kc + tg];
            a[mt][1] = Qs[(r + 8) * QK_LDS + kc + tg];
            a[mt][2] = Qs[(r) * QK_LDS + kc + tg + 4];
            a[mt][3] = Qs[(r + 8) * QK_LDS + kc + tg + 4];
        }
        unsigned b[8][2];
#pragma unroll
        for (int nt = 0; nt < 8; ++nt) {
            int n = wn * 64 + nt * 8 + g;
            b[nt][0] = Ks[n * QK_LDS + kc + tg];
            b[nt][1] = Ks[n * QK_LDS + kc + tg + 4];
        }
#pragma unroll
        for (int mt = 0; mt < 2; ++mt)
#pragma unroll
            for (int nt = 0; nt < 8; ++nt) {
                asm volatile(
                    "mma.sync.aligned.m16n8k8.row.col.f32.tf32.tf32.f32 "
                    "{%0,%1,%2,%3}, {%4,%5,%6,%7}, {%8,%9}, {%0,%1,%2,%3};"
                    : "+f"(acc[mt][nt][0]), "+f"(acc[mt][nt][1]),
                      "+f"(acc[mt][nt][2]), "+f"(acc[mt][nt][3])
                    : "r"(a[mt][0]), "r"(a[mt][1]), "r"(a[mt][2]), "r"(a[mt][3]),
                      "r"(b[nt][0]), "r"(b[nt][1]));
            }
    }
}

__global__ __launch_bounds__(256) void qk_screen(
    const float* __restrict__ Q, const float* __restrict__ K,
    unsigned short* __restrict__ cand, int* __restrict__ ccnt,
    float* __restrict__ rmaxf)
{
    extern __shared__ unsigned sm[];
    unsigned* Qs = sm;
    unsigned* Ks = sm + 128 * QK_LDS;
    unsigned short* jl = (unsigned short*)(sm + 2 * 128 * QK_LDS);
    unsigned* rmaxs = (unsigned*)(jl + 128 * CAPS);
    float* thrs = (float*)(rmaxs + 128);
    int* cnts = (int*)(thrs + 128);

    int tid = threadIdx.x;
    int wid = tid >> 5, lane = tid & 31;
    int wm = wid & 3;
    int wn = wid >> 2;
    int g = lane >> 2;
    int tg = lane & 3;
    int qb = lane & ~3;

    int bh = blockIdx.z;
    int q0 = blockIdx.x * 128;

    for (int r = tid; r < 128; r += 256) { rmaxs[r] = 0u; cnts[r] = 0; }

    const float* Qg = Q + ((long)bh * Ss + q0) * DHh;
#pragma unroll
    for (int p = 0; p < 8; ++p) {
        int r = (tid >> 4) + p * 16;
        int c = (tid & 15) * 4;
        float4 v = *(const float4*)(Qg + r * DHh + c);
        unsigned* q = Qs + r * QK_LDS + c;
        q[0] = f2tf32(v.x); q[1] = f2tf32(v.y);
        q[2] = f2tf32(v.z); q[3] = f2tf32(v.w);
    }
    __syncthreads();

    float acc[2][8][4];

    // pass A: row maxima
    for (int t = 0; t < 16; ++t) {
        const float* Kg = K + ((long)bh * Ss + t * 128) * DHh;
#pragma unroll
        for (int p = 0; p < 8; ++p) {
            int r = (tid >> 4) + p * 16;
            int c = (tid & 15) * 4;
            float4 v = *(const float4*)(Kg + r * DHh + c);
            unsigned* kk = Ks + r * QK_LDS + c;
            kk[0] = f2tf32(v.x); kk[1] = f2tf32(v.y);
            kk[2] = f2tf32(v.z); kk[3] = f2tf32(v.w);
        }
        __syncthreads();

        tile_mma(Qs, Ks, wm, wn, g, tg, acc);

#pragma unroll
        for (int mt = 0; mt < 2; ++mt) {
            float m0 = -3e38f, m1 = -3e38f;
#pragma unroll
            for (int nt = 0; nt < 8; ++nt) {
                m0 = fmaxf(m0, fmaxf(acc[mt][nt][0], acc[mt][nt][1]));
                m1 = fmaxf(m1, fmaxf(acc[mt][nt][2], acc[mt][nt][3]));
            }
#pragma unroll
            for (int off = 1; off <= 2; off <<= 1) {
                m0 = fmaxf(m0, __shfl_xor_sync(0xffffffffu, m0, off));
                m1 = fmaxf(m1, __shfl_xor_sync(0xffffffffu, m1, off));
            }
            if (tg == 0) {
                atomicMax(&rmaxs[wm * 32 + mt * 16 + g], enc_f(m0));
                atomicMax(&rmaxs[wm * 32 + mt * 16 + g + 8], enc_f(m1));
            }
        }
        __syncthreads();
    }

    for (int r = tid; r < 128; r += 256) thrs[r] = dec_f(rmaxs[r]) - 1.02f;
    __syncthreads();

    // pass B: screen vs final threshold
    for (int t = 0; t < 16; ++t) {
        const float* Kg = K + ((long)bh * Ss + t * 128) * DHh;
#pragma unroll
        for (int p = 0; p < 8; ++p) {
            int r = (tid >> 4) + p * 16;
            int c = (tid & 15) * 4;
            float4 v = *(const float4*)(Kg + r * DHh + c);
            unsigned* kk = Ks + r * QK_LDS + c;
            kk[0] = f2tf32(v.x); kk[1] = f2tf32(v.y);
            kk[2] = f2tf32(v.z); kk[3] = f2tf32(v.w);
        }
        __syncthreads();

        tile_mma(Qs, Ks, wm, wn, g, tg, acc);

        for (int phase = 0; phase < 2; ++phase) {
            if (wn == phase) {
#pragma unroll
                for (int mt = 0; mt < 2; ++mt) {
#pragma unroll
                    for (int half = 0; half < 2; ++half) {
                        int r = wm * 32 + mt * 16 + g + half * 8;
                        float thr = thrs[r];
                        unsigned m = 0;
#pragma unroll
                        for (int nt = 0; nt < 8; ++nt) {
#pragma unroll
                            for (int ee = 0; ee < 2; ++ee)
                                if (acc[mt][nt][half * 2 + ee] > thr)
                                    m |= 1u << (nt * 2 + ee);
                        }
                        int c = __popc(m);
                        int c0 = __shfl_sync(0xffffffffu, c, qb);
                        int c1 = __shfl_sync(0xffffffffu, c, qb + 1);
                        int c2 = __shfl_sync(0xffffffffu, c, qb + 2);
                        int c3 = __shfl_sync(0xffffffffu, c, qb + 3);
                        int pre = (tg > 0 ? c0 : 0) + (tg > 1 ? c1 : 0) + (tg > 2 ? c2 : 0);
                        int tot = c0 + c1 + c2 + c3;
                        int base = cnts[r];
                        int pos = base + pre;
                        while (m) {
                            int bit = __ffs(m) - 1; m &= m - 1;
                            int j = t * 128 + wn * 64 + (bit >> 1) * 8 + tg * 2 + (bit & 1);
                            if (pos < CAPS) jl[r * CAPS + pos] = (unsigned short)j;
                            ++pos;
                        }
                        __syncwarp();
                        if (tg == 0) cnts[r] = base + tot;
                        __syncwarp();
                    }
                }
            }
            __syncthreads();
        }
    }

    long rowg0 = (long)bh * Ss + q0;
    for (int r = tid; r < 128; r += 256) {
        ccnt[rowg0 + r] = cnts[r];
        rmaxf[rowg0 + r] = dec_f(rmaxs[r]);
    }
    __syncthreads();
    for (int r = wid; r < 128; r += 8) {
        int c = min(cnts[r], CAPS);
        unsigned short* dst = cand + (rowg0 + r) * CAPS;
        for (int e = lane; e < c; e += 32) dst[e] = jl[r * CAPS + e];
    }
}

// ---------------------------------------------------------------------------
// Finish: exact fp32 candidate logits, Michelot tau, heads, avg.
// Overflowing heads (window pop > CAPS; rare) are deferred and solved by the
// whole block on a shared z-row (coalesced, deterministic, ~20us each).
// ---------------------------------------------------------------------------
__device__ __forceinline__ void block_zrow(
    const float* KbhH, float qh0, float qh1,
    int w, int lane, float* s_zrow)
{
    for (int j0 = w * 256; j0 < w * 256 + 256; j0 += 4) {
        float p[4];
#pragma unroll
        for (int u = 0; u < 4; ++u) {
            const float* Kr = KbhH + (long)(j0 + u) * DHh;
            p[u] = qh0 * Kr[lane] + qh1 * Kr[lane + 32];
        }
#pragma unroll
        for (int off = 16; off; off >>= 1)
#pragma unroll
            for (int u = 0; u < 4; ++u)
                p[u] += __shfl_xor_sync(0xffffffffu, p[u], off);
        if (lane == 0) {
#pragma unroll
            for (int u = 0; u < 4; ++u) s_zrow[j0 + u] = p[u];
        }
    }
}

__global__ __launch_bounds__(256) void sparse_final(
    const unsigned short* __restrict__ cand, const int* __restrict__ ccnt,
    const float* __restrict__ rmaxf,
    const float* __restrict__ Q, const float* __restrict__ K,
    const float* __restrict__ V,
    float* __restrict__ heads, float* __restrict__ avg_out)
{
    __shared__ float s_z[Hh][CAPS];
    __shared__ short s_j[Hh][CAPS];
    __shared__ float s_tau[Hh];
    __shared__ int   s_cnt[Hh];
    __shared__ int   s_over[Hh];
    __shared__ float s_zrow[Ss];
    __shared__ float s_part[8];
    __shared__ int   s_partc[8];
    __shared__ float s_bcast;

    int row = blockIdx.x;
    int b = row >> 11;
    int i = row & 2047;
    int tid = threadIdx.x;
    int w = tid >> 5;
    int lane = tid & 31;

    long bhrow = ((long)b * Hh + w) * Ss + i;
    const float* Qrow = Q + bhrow * DHh;
    const float* Kbh  = K + (((long)b * Hh + w) * Ss) * (long)DHh;
    const float* Vb   = V + (long)b * Ss * DHh;
    float q0 = Qrow[lane], q1 = Qrow[lane + 32];

    int n = ccnt[bhrow];
    float rv[8];
#pragma unroll
    for (int k = 0; k < 8; ++k) rv[k] = 0.0f;

    if (n <= CAPS) {
        if (lane == 0) s_over[w] = 0;
        const unsigned short* cr = cand + bhrow * CAPS;
        for (int e = lane; e < n; e += 32) s_j[w][e] = (short)cr[e];
        __syncwarp();

        int e = 0;
        for (; e + 2 <= n; e += 2) {
            int j0 = s_j[w][e], j1 = s_j[w][e + 1];
            const float* K0 = Kbh + (long)j0 * DHh;
            const float* K1 = Kbh + (long)j1 * DHh;
            float p0 = q0 * K0[lane] + q1 * K0[lane + 32];
            float p1 = q0 * K1[lane] + q1 * K1[lane + 32];
#pragma unroll
            for (int off = 16; off; off >>= 1) {
                p0 += __shfl_xor_sync(0xffffffffu, p0, off);
                p1 += __shfl_xor_sync(0xffffffffu, p1, off);
            }
            if (lane == 0) { s_z[w][e] = p0; s_z[w][e + 1] = p1; }
        }
        if (e < n) {
            int j0 = s_j[w][e];
            const float* K0 = Kbh + (long)j0 * DHh;
            float p0 = q0 * K0[lane] + q1 * K0[lane + 32];
#pragma unroll
            for (int off = 16; off; off >>= 1)
                p0 += __shfl_xor_sync(0xffffffffu, p0, off);
            if (lane == 0) s_z[w][e] = p0;
        }
        __syncwarp();

        float tau = rmaxf[bhrow] - 1.02f;
        for (int it = 0; it < 48; ++it) {
            float s = 0.0f; int c = 0;
            for (int e2 = lane; e2 < n; e2 += 32) {
                float zz = s_z[w][e2];
                if (zz > tau) { s += zz; c++; }
            }
#pragma unroll
            for (int off = 16; off; off >>= 1) {
                s += __shfl_xor_sync(0xffffffffu, s, off);
                c += __shfl_xor_sync(0xffffffffu, c, off);
            }
            float nt2 = (s - 1.0f) / (float)c;
            if (nt2 == tau) break;
            tau = nt2;
        }
        if (lane == 0) { s_tau[w] = tau; s_cnt[w] = n; }

        float o0 = 0.0f, o1 = 0.0f;
        for (int e2 = 0; e2 < n; ++e2) {
            float p = s_z[w][e2] - tau;
            if (p > 0.0f) {
                const float* Vr = Vb + (long)s_j[w][e2] * DHh;
                o0 += p * Vr[lane];
                o1 += p * Vr[lane + 32];
            }
        }
        long hbase = (long)row * Dd + w * DHh;
        heads[hbase + lane] = o0;
        heads[hbase + lane + 32] = o1;
    } else {
        if (lane == 0) { s_over[w] = 1; s_cnt[w] = 0; s_tau[w] = 0.0f; }
    }

    __syncthreads();

    // deferred overflow heads: block-cooperative exact solve on shared z-row
    for (int h = 0; h < Hh; ++h) {
        if (!s_over[h]) continue;

        long bhrowH = ((long)b * Hh + h) * Ss + i;
        const float* QrowH = Q + bhrowH * DHh;
        const float* KbhH  = K + (((long)b * Hh + h) * Ss) * (long)DHh;
        float qh0 = QrowH[lane], qh1 = QrowH[lane + 32];

        block_zrow(KbhH, qh0, qh1, w, lane, s_zrow);
        __syncthreads();

        float tau = rmaxf[bhrowH] - 1.02f;
        for (int it = 0; it < 48; ++it) {
            float s = 0.0f; int c = 0;
#pragma unroll
            for (int k = 0; k < 8; ++k) {
                float zz = s_zrow[tid + k * 256];
                if (zz > tau) { s += zz; c++; }
            }
#pragma unroll
            for (int off = 16; off; off >>= 1) {
                s += __shfl_xor_sync(0xffffffffu, s, off);
                c += __shfl_xor_sync(0xffffffffu, c, off);
            }
            if (lane == 0) { s_part[w] = s; s_partc[w] = c; }
            __syncthreads();
            if (tid == 0) {
                float S = 0.0f; int C = 0;
#pragma unroll
                for (int k = 0; k < 8; ++k) { S += s_part[k]; C += s_partc[k]; }
                s_bcast = (S - 1.0f) / (float)C;
            }
            __syncthreads();
            float nt2 = s_bcast;
            bool done = (nt2 == tau);
            tau = nt2;
            __syncthreads();      // s_part safe to overwrite next iteration
            if (done) break;
        }
        if (tid == 0) s_tau[h] = tau;

        // heads: threads 0..63 own one output dim, coalesced V stream
        if (tid < DHh) {
            float o = 0.0f;
            for (int j = 0; j < Ss; ++j) {
                float p = s_zrow[j] - tau;
                if (p > 0.0f) o += p * Vb[(long)j * DHh + tid];
            }
            heads[(long)row * Dd + h * DHh + tid] = o;
        }

        // avg contribution from this head (ownership: thread owns j%256==tid)
#pragma unroll
        for (int k = 0; k < 8; ++k) {
            float p = s_zrow[tid + k * 256] - tau;
            if (p > 0.0f) rv[k] += p;
        }
        __syncthreads();   // s_zrow free for next overflow head
    }

    // avg_attention: ownership scan over normal heads' candidate lists
#pragma unroll
    for (int h = 0; h < Hh; ++h) {
        int c = s_cnt[h];
        float th = s_tau[h];
        for (int e = 0; e < c; ++e) {
            int j = s_j[h][e];
            if ((j & 255) == tid) {
                float p = s_z[h][e] - th;
                if (p > 0.0f) rv[j >> 8] += p;
            }
        }
    }
    long abase = ((long)b * Ss + i) * (long)Ss;
#pragma unroll
    for (int k = 0; k < 8; ++k)
        avg_out[abase + tid + k * 256] = 0.125f * rv[k];
}

// ---------------------------------------------------------------------------
extern "C" void kernel_launch(void* const* d_in, const int* in_sizes, int n_in,
                              void* d_out, int out_size)
{
    const float* x    = (const float*)d_in[0];
    const float* Wq   = (const float*)d_in[1];
    const float* bq   = (const float*)d_in[2];
    const float* Wk   = (const float*)d_in[3];
    const float* bk   = (const float*)d_in[4];
    const float* Wv   = (const float*)d_in[5];
    const float* bv   = (const float*)d_in[6];
    const float* Wout = (const float*)d_in[7];
    const float* bout = (const float*)d_in[8];

    float* out   = (float*)d_out;
    float* x_out = out;                              // [B,S,D]
    float* avg   = out + (long)Bb * Ss * Dd;         // [B,S,S]

    float *Qp, *Kp, *Vp, *Hp, *Rp;
    unsigned short* Cp;
    int* Np;
    cudaGetSymbolAddress((void**)&Qp, g_Q);
    cudaGetSymbolAddress((void**)&Kp, g_K);
    cudaGetSymbolAddress((void**)&Vp, g_V);
    cudaGetSymbolAddress((void**)&Hp, g_heads);
    cudaGetSymbolAddress((void**)&Cp, g_cand);
    cudaGetSymbolAddress((void**)&Np, g_ccnt);
    cudaGetSymbolAddress((void**)&Rp, g_rmax);

    cudaFuncSetAttribute(qk_screen,
                         cudaFuncAttributeMaxDynamicSharedMemorySize,
                         SCR_SMEM);

    proj_qkv<<<dim3(32, 17, 1), 256>>>(x, Wq, bq, Wk, bk, Wv, bv, Qp, Kp, Vp);
    qk_screen<<<dim3(Ss / 128, 1, Bb * Hh), 256, SCR_SMEM>>>(
        Qp, Kp, Cp, Np, Rp);
    sparse_final<<<Bb * Ss, 256>>>(Cp, Np, Rp, Qp, Kp, Vp, Hp, avg);
    sgemm_128x64<<<dim3(32, 8, 1), 256>>>(Hp, Dd, Wout, Dd, bout, x_out, Dd, Dd);
}

// round 11
// speedup vs baseline: 3.0819x; 1.0684x over previous
#include <cuda_runtime.h>

#define Bb 2
#define Ss 2048
#define Dd 512
#define Hh 8
#define DHh 64
#define CAPS 128     // candidate cap per row

// Scratch (device globals: no runtime allocation allowed)
__device__ float          g_Q[Bb * Hh * Ss * DHh];       // [B,H,S,dh]  8 MB
__device__ float          g_K[Bb * Hh * Ss * DHh];       // [B,H,S,dh]  8 MB
__device__ float          g_V[Bb * Ss * DHh];            // [B,S,dh]    1 MB
__device__ float          g_heads[Bb * Ss * Dd];         // [B,S,D]     8 MB
__device__ unsigned short g_cand[Bb * Hh * Ss * CAPS];   // cand indices
__device__ int            g_ccnt[Bb * Hh * Ss];          // cand counts
__device__ float          g_rmax[Bb * Hh * Ss];          // tf32 row maxes

__device__ __forceinline__ unsigned enc_f(float f) {
    unsigned b = __float_as_uint(f);
    return (f >= 0.0f) ? (b | 0x80000000u) : ~b;
}
__device__ __forceinline__ float dec_f(unsigned u) {
    return (u & 0x80000000u) ? __uint_as_float(u & 0x7fffffffu)
                             : __uint_as_float(~u);
}
__device__ __forceinline__ unsigned f2tf32(float f) {
    unsigned u;
    asm("cvt.rna.tf32.f32 %0, %1;" : "=r"(u) : "f"(f));
    return u;
}

#define MMA3(d, a, b) asm volatile( \
    "mma.sync.aligned.m16n8k8.row.col.f32.tf32.tf32.f32 " \
    "{%0,%1,%2,%3}, {%4,%5,%6,%7}, {%8,%9}, {%0,%1,%2,%3};" \
    : "+f"(d[0]), "+f"(d[1]), "+f"(d[2]), "+f"(d[3]) \
    : "r"(a[0]), "r"(a[1]), "r"(a[2]), "r"(a[3]), "r"(b[0]), "r"(b[1]))

// ---------------------------------------------------------------------------
// 3xTF32 GEMM core: C[128x64 tile] = A(MxK) @ W(KxN) + bias, K = Dd = 512.
// Split a = hi + lo (tf32 each); acc += ah*bl + al*bh + ah*bh (fp32 acc).
// Dropped lo*lo term ~2^-22 relative. 8 warps = 4(m) x 2(n); warp tile 32x32.
// Fragment layouts identical to the validated qk_screen patterns.
// smem: Ah/Al [128][36] u32, Bh/Bl [64][36] u32 (conflict-free frag reads).
// ---------------------------------------------------------------------------
#define G3_SMEM ((2 * 128 * 36 + 2 * 64 * 36) * 4)   // 55296 B

__device__ __forceinline__ void gemm3t_tile(
    const float* __restrict__ A, int lda,
    const float* __restrict__ W, int ldw,
    const float* __restrict__ bias,
    float* __restrict__ C,
    int m0, int n0, int ldc, int headMajor,
    unsigned* Ah, unsigned* Al, unsigned* Bh, unsigned* Bl)
{
    int tid = threadIdx.x;
    int wid = tid >> 5, lane = tid & 31;
    int wm = wid & 3, wn = wid >> 2;
    int g = lane >> 2, tg = lane & 3;

    float acc[2][4][4];
#pragma unroll
    for (int mt = 0; mt < 2; ++mt)
#pragma unroll
        for (int nt = 0; nt < 4; ++nt)
#pragma unroll
            for (int e = 0; e < 4; ++e) acc[mt][nt][e] = 0.0f;

    int arow = tid >> 1;              // A: 128 rows x 32 k, 4 float4/thread
    int acb = (tid & 1) * 16;
    int bn = tid & 63;                // B: 32 k x 64 n, 8 scalars/thread
    int bkb = (tid >> 6) * 8;

    for (int k0 = 0; k0 < Dd; k0 += 32) {
        // stage A (hi/lo split), coalesced 16B reads
#pragma unroll
        for (int p = 0; p < 4; ++p) {
            int c = acb + p * 4;
            float4 v = *(const float4*)(A + (long)(m0 + arow) * lda + k0 + c);
            float vv[4] = {v.x, v.y, v.z, v.w};
#pragma unroll
            for (int u = 0; u < 4; ++u) {
                unsigned hi = f2tf32(vv[u]);
                Ah[arow * 36 + c + u] = hi;
                Al[arow * 36 + c + u] = f2tf32(vv[u] - __uint_as_float(hi));
            }
        }
        // stage B transposed to [n][k] (per-u reads coalesced across lanes)
#pragma unroll
        for (int u = 0; u < 8; ++u) {
            float v = W[(long)(k0 + bkb + u) * ldw + n0 + bn];
            unsigned hi = f2tf32(v);
            Bh[bn * 36 + bkb + u] = hi;
            Bl[bn * 36 + bkb + u] = f2tf32(v - __uint_as_float(hi));
        }
        __syncthreads();

#pragma unroll
        for (int kc = 0; kc < 32; kc += 8) {
            unsigned ah[2][4], al[2][4], bh[4][2], bl[4][2];
#pragma unroll
            for (int mt = 0; mt < 2; ++mt) {
                int r = wm * 32 + mt * 16 + g;
                ah[mt][0] = Ah[r * 36 + kc + tg];
                ah[mt][1] = Ah[(r + 8) * 36 + kc + tg];
                ah[mt][2] = Ah[r * 36 + kc + tg + 4];
                ah[mt][3] = Ah[(r + 8) * 36 + kc + tg + 4];
                al[mt][0] = Al[r * 36 + kc + tg];
                al[mt][1] = Al[(r + 8) * 36 + kc + tg];
                al[mt][2] = Al[r * 36 + kc + tg + 4];
                al[mt][3] = Al[(r + 8) * 36 + kc + tg + 4];
            }
#pragma unroll
            for (int nt = 0; nt < 4; ++nt) {
                int n = wn * 32 + nt * 8 + g;
                bh[nt][0] = Bh[n * 36 + kc + tg];
                bh[nt][1] = Bh[n * 36 + kc + tg + 4];
                bl[nt][0] = Bl[n * 36 + kc + tg];
                bl[nt][1] = Bl[n * 36 + kc + tg + 4];
            }
#pragma unroll
            for (int mt = 0; mt < 2; ++mt)
#pragma unroll
                for (int nt = 0; nt < 4; ++nt) {
                    MMA3(acc[mt][nt], ah[mt], bl[nt]);   // fixed order:
                    MMA3(acc[mt][nt], al[mt], bh[nt]);   // small terms first
                    MMA3(acc[mt][nt], ah[mt], bh[nt]);
                }
        }
        __syncthreads();
    }

    // epilogue: float2 stores, bias in fp32
    int cb = wn * 32 + tg * 2;
#pragma unroll
    for (int mt = 0; mt < 2; ++mt) {
#pragma unroll
        for (int nt = 0; nt < 4; ++nt) {
            int r0 = m0 + wm * 32 + mt * 16 + g;
            int c = cb + nt * 8;
            float2 b2 = *(const float2*)(bias + n0 + c);
            float o0 = acc[mt][nt][0] + b2.x;
            float o1 = acc[mt][nt][1] + b2.y;
            float o2 = acc[mt][nt][2] + b2.x;
            float o3 = acc[mt][nt][3] + b2.y;
            if (headMajor) {
                int hh = n0 >> 6;
                int bb0 = r0 >> 11, ss0 = r0 & 2047;
                *(float2*)(C + ((((long)bb0 * Hh + hh) * Ss) + ss0) * DHh + c) =
                    make_float2(o0, o1);
                int r1 = r0 + 8;
                int bb1 = r1 >> 11, ss1 = r1 & 2047;
                *(float2*)(C + ((((long)bb1 * Hh + hh) * Ss) + ss1) * DHh + c) =
                    make_float2(o2, o3);
            } else {
                *(float2*)(C + (long)r0 * ldc + n0 + c) = make_float2(o0, o1);
                *(float2*)(C + (long)(r0 + 8) * ldc + n0 + c) = make_float2(o2, o3);
            }
        }
    }
}

// Fused Q/K/V projection via 3xtf32: grid (32, 17)
__global__ __launch_bounds__(256) void proj3t(
    const float* __restrict__ x,
    const float* __restrict__ Wq, const float* __restrict__ bq,
    const float* __restrict__ Wk, const float* __restrict__ bk,
    const float* __restrict__ Wv, const float* __restrict__ bv,
    float* __restrict__ Qo, float* __restrict__ Ko, float* __restrict__ Vo)
{
    extern __shared__ unsigned sm3[];
    unsigned* Ah = sm3;
    unsigned* Al = sm3 + 128 * 36;
    unsigned* Bh = sm3 + 2 * 128 * 36;
    unsigned* Bl = Bh + 64 * 36;

    int y = blockIdx.y;
    int m0 = blockIdx.x * 128;
    if (y < 8)
        gemm3t_tile(x, Dd, Wq, Dd, bq, Qo, m0, y * 64, 0, 1, Ah, Al, Bh, Bl);
    else if (y < 16)
        gemm3t_tile(x, Dd, Wk, Dd, bk, Ko, m0, (y - 8) * 64, 0, 1, Ah, Al, Bh, Bl);
    else
        gemm3t_tile(x, Dd, Wv, DHh, bv, Vo, m0, 0, DHh, 0, Ah, Al, Bh, Bl);
}

// Output projection via 3xtf32: grid (32, 8)
__global__ __launch_bounds__(256) void wout3t(
    const float* __restrict__ A, const float* __restrict__ W,
    const float* __restrict__ bias, float* __restrict__ C)
{
    extern __shared__ unsigned sm3[];
    unsigned* Ah = sm3;
    unsigned* Al = sm3 + 128 * 36;
    unsigned* Bh = sm3 + 2 * 128 * 36;
    unsigned* Bl = Bh + 64 * 36;
    gemm3t_tile(A, Dd, W, Dd, bias, C,
                blockIdx.x * 128, blockIdx.y * 64, Dd, 0, Ah, Al, Bh, Bl);
}

// ---------------------------------------------------------------------------
// Fused QK + TWO-PASS screening (final threshold; no logits materialization).
// (unchanged from R10 — validated)
// ---------------------------------------------------------------------------
#define QK_LDS 68
#define SCR_SMEM (2 * 128 * QK_LDS * 4 + 128 * CAPS * 2 + 128 * 4 + 128 * 4 + 128 * 4)

__device__ __forceinline__ void tile_mma(
    const unsigned* Qs, const unsigned* Ks,
    int wm, int wn, int g, int tg, float acc[2][8][4])
{
#pragma unroll
    for (int mt = 0; mt < 2; ++mt)
#pragma unroll
        for (int nt = 0; nt < 8; ++nt)
#pragma unroll
            for (int e = 0; e < 4; ++e) acc[mt][nt][e] = 0.0f;

#pragma unroll
    for (int ks = 0; ks < 8; ++ks) {
        int kc = ks * 8;
        unsigned a[2][4];
#pragma unroll
        for (int mt = 0; mt < 2; ++mt) {
            int r = wm * 32 + mt * 16 + g;
            a[mt][0] = Qs[(r) * QK_LDS + kc + tg];
            a[mt][1] = Qs[(r + 8) * QK_LDS + kc + tg];
            a[mt][2] = Qs[(r) * QK_LDS + kc + tg + 4];
            a[mt][3] = Qs[(r + 8) * QK_LDS + kc + tg + 4];
        }
        unsigned b[8][2];
#pragma unroll
        for (int nt = 0; nt < 8; ++nt) {
            int n = wn * 64 + nt * 8 + g;
            b[nt][0] = Ks[n * QK_LDS + kc + tg];
            b[nt][1] = Ks[n * QK_LDS + kc + tg + 4];
        }
#pragma unroll
        for (int mt = 0; mt < 2; ++mt)
#pragma unroll
            for (int nt = 0; nt < 8; ++nt) {
                asm volatile(
                    "mma.sync.aligned.m16n8k8.row.col.f32.tf32.tf32.f32 "
                    "{%0,%1,%2,%3}, {%4,%5,%6,%7}, {%8,%9}, {%0,%1,%2,%3};"
                    : "+f"(acc[mt][nt][0]), "+f"(acc[mt][nt][1]),
                      "+f"(acc[mt][nt][2]), "+f"(acc[mt][nt][3])
                    : "r"(a[mt][0]), "r"(a[mt][1]), "r"(a[mt][2]), "r"(a[mt][3]),
                      "r"(b[nt][0]), "r"(b[nt][1]));
            }
    }
}

__global__ __launch_bounds__(256) void qk_screen(
    const float* __restrict__ Q, const float* __restrict__ K,
    unsigned short* __restrict__ cand, int* __restrict__ ccnt,
    float* __restrict__ rmaxf)
{
    extern __shared__ unsigned sm[];
    unsigned* Qs = sm;
    unsigned* Ks = sm + 128 * QK_LDS;
    unsigned short* jl = (unsigned short*)(sm + 2 * 128 * QK_LDS);
    unsigned* rmaxs = (unsigned*)(jl + 128 * CAPS);
    float* thrs = (float*)(rmaxs + 128);
    int* cnts = (int*)(thrs + 128);

    int tid = threadIdx.x;
    int wid = tid >> 5, lane = tid & 31;
    int wm = wid & 3;
    int wn = wid >> 2;
    int g = lane >> 2;
    int tg = lane & 3;
    int qb = lane & ~3;

    int bh = blockIdx.z;
    int q0 = blockIdx.x * 128;

    for (int r = tid; r < 128; r += 256) { rmaxs[r] = 0u; cnts[r] = 0; }

    const float* Qg = Q + ((long)bh * Ss + q0) * DHh;
#pragma unroll
    for (int p = 0; p < 8; ++p) {
        int r = (tid >> 4) + p * 16;
        int c = (tid & 15) * 4;
        float4 v = *(const float4*)(Qg + r * DHh + c);
        unsigned* q = Qs + r * QK_LDS + c;
        q[0] = f2tf32(v.x); q[1] = f2tf32(v.y);
        q[2] = f2tf32(v.z); q[3] = f2tf32(v.w);
    }
    __syncthreads();

    float acc[2][8][4];

    // pass A: row maxima
    for (int t = 0; t < 16; ++t) {
        const float* Kg = K + ((long)bh * Ss + t * 128) * DHh;
#pragma unroll
        for (int p = 0; p < 8; ++p) {
            int r = (tid >> 4) + p * 16;
            int c = (tid & 15) * 4;
            float4 v = *(const float4*)(Kg + r * DHh + c);
            unsigned* kk = Ks + r * QK_LDS + c;
            kk[0] = f2tf32(v.x); kk[1] = f2tf32(v.y);
            kk[2] = f2tf32(v.z); kk[3] = f2tf32(v.w);
        }
        __syncthreads();

        tile_mma(Qs, Ks, wm, wn, g, tg, acc);

#pragma unroll
        for (int mt = 0; mt < 2; ++mt) {
            float m0 = -3e38f, m1 = -3e38f;
#pragma unroll
            for (int nt = 0; nt < 8; ++nt) {
                m0 = fmaxf(m0, fmaxf(acc[mt][nt][0], acc[mt][nt][1]));
                m1 = fmaxf(m1, fmaxf(acc[mt][nt][2], acc[mt][nt][3]));
            }
#pragma unroll
            for (int off = 1; off <= 2; off <<= 1) {
                m0 = fmaxf(m0, __shfl_xor_sync(0xffffffffu, m0, off));
                m1 = fmaxf(m1, __shfl_xor_sync(0xffffffffu, m1, off));
            }
            if (tg == 0) {
                atomicMax(&rmaxs[wm * 32 + mt * 16 + g], enc_f(m0));
                atomicMax(&rmaxs[wm * 32 + mt * 16 + g + 8], enc_f(m1));
            }
        }
        __syncthreads();
    }

    for (int r = tid; r < 128; r += 256) thrs[r] = dec_f(rmaxs[r]) - 1.02f;
    __syncthreads();

    // pass B: screen vs final threshold
    for (int t = 0; t < 16; ++t) {
        const float* Kg = K + ((long)bh * Ss + t * 128) * DHh;
#pragma unroll
        for (int p = 0; p < 8; ++p) {
            int r = (tid >> 4) + p * 16;
            int c = (tid & 15) * 4;
            float4 v = *(const float4*)(Kg + r * DHh + c);
            unsigned* kk = Ks + r * QK_LDS + c;
            kk[0] = f2tf32(v.x); kk[1] = f2tf32(v.y);
            kk[2] = f2tf32(v.z); kk[3] = f2tf32(v.w);
        }
        __syncthreads();

        tile_mma(Qs, Ks, wm, wn, g, tg, acc);

        for (int phase = 0; phase < 2; ++phase) {
            if (wn == phase) {
#pragma unroll
                for (int mt = 0; mt < 2; ++mt) {
#pragma unroll
                    for (int half = 0; half < 2; ++half) {
                        int r = wm * 32 + mt * 16 + g + half * 8;
                        float thr = thrs[r];
                        unsigned m = 0;
#pragma unroll
                        for (int nt = 0; nt < 8; ++nt) {
#pragma unroll
                            for (int ee = 0; ee < 2; ++ee)
                                if (acc[mt][nt][half * 2 + ee] > thr)
                                    m |= 1u << (nt * 2 + ee);
                        }
                        int c = __popc(m);
                        int c0 = __shfl_sync(0xffffffffu, c, qb);
                        int c1 = __shfl_sync(0xffffffffu, c, qb + 1);
                        int c2 = __shfl_sync(0xffffffffu, c, qb + 2);
                        int c3 = __shfl_sync(0xffffffffu, c, qb + 3);
                        int pre = (tg > 0 ? c0 : 0) + (tg > 1 ? c1 : 0) + (tg > 2 ? c2 : 0);
                        int tot = c0 + c1 + c2 + c3;
                        int base = cnts[r];
                        int pos = base + pre;
                        while (m) {
                            int bit = __ffs(m) - 1; m &= m - 1;
                            int j = t * 128 + wn * 64 + (bit >> 1) * 8 + tg * 2 + (bit & 1);
                            if (pos < CAPS) jl[r * CAPS + pos] = (unsigned short)j;
                            ++pos;
                        }
                        __syncwarp();
                        if (tg == 0) cnts[r] = base + tot;
                        __syncwarp();
                    }
                }
            }
            __syncthreads();
        }
    }

    long rowg0 = (long)bh * Ss + q0;
    for (int r = tid; r < 128; r += 256) {
        ccnt[rowg0 + r] = cnts[r];
        rmaxf[rowg0 + r] = dec_f(rmaxs[r]);
    }
    __syncthreads();
    for (int r = wid; r < 128; r += 8) {
        int c = min(cnts[r], CAPS);
        unsigned short* dst = cand + (rowg0 + r) * CAPS;
        for (int e = lane; e < c; e += 32) dst[e] = jl[r * CAPS + e];
    }
}

// ---------------------------------------------------------------------------
// Finish: exact fp32 candidate logits, Michelot tau, heads, avg.
// (unchanged from R10 — validated, overflow path bounded ~20us/head)
// ---------------------------------------------------------------------------
__device__ __forceinline__ void block_zrow(
    const float* KbhH, float qh0, float qh1,
    int w, int lane, float* s_zrow)
{
    for (int j0 = w * 256; j0 < w * 256 + 256; j0 += 4) {
        float p[4];
#pragma unroll
        for (int u = 0; u < 4; ++u) {
            const float* Kr = KbhH + (long)(j0 + u) * DHh;
            p[u] = qh0 * Kr[lane] + qh1 * Kr[lane + 32];
        }
#pragma unroll
        for (int off = 16; off; off >>= 1)
#pragma unroll
            for (int u = 0; u < 4; ++u)
                p[u] += __shfl_xor_sync(0xffffffffu, p[u], off);
        if (lane == 0) {
#pragma unroll
            for (int u = 0; u < 4; ++u) s_zrow[j0 + u] = p[u];
        }
    }
}

__global__ __launch_bounds__(256) void sparse_final(
    const unsigned short* __restrict__ cand, const int* __restrict__ ccnt,
    const float* __restrict__ rmaxf,
    const float* __restrict__ Q, const float* __restrict__ K,
    const float* __restrict__ V,
    float* __restrict__ heads, float* __restrict__ avg_out)
{
    __shared__ float s_z[Hh][CAPS];
    __shared__ short s_j[Hh][CAPS];
    __shared__ float s_tau[Hh];
    __shared__ int   s_cnt[Hh];
    __shared__ int   s_over[Hh];
    __shared__ float s_zrow[Ss];
    __shared__ float s_part[8];
    __shared__ int   s_partc[8];
    __shared__ float s_bcast;

    int row = blockIdx.x;
    int b = row >> 11;
    int i = row & 2047;
    int tid = threadIdx.x;
    int w = tid >> 5;
    int lane = tid & 31;

    long bhrow = ((long)b * Hh + w) * Ss + i;
    const float* Qrow = Q + bhrow * DHh;
    const float* Kbh  = K + (((long)b * Hh + w) * Ss) * (long)DHh;
    const float* Vb   = V + (long)b * Ss * DHh;
    float q0 = Qrow[lane], q1 = Qrow[lane + 32];

    int n = ccnt[bhrow];
    float rv[8];
#pragma unroll
    for (int k = 0; k < 8; ++k) rv[k] = 0.0f;

    if (n <= CAPS) {
        if (lane == 0) s_over[w] = 0;
        const unsigned short* cr = cand + bhrow * CAPS;
        for (int e = lane; e < n; e += 32) s_j[w][e] = (short)cr[e];
        __syncwarp();

        int e = 0;
        for (; e + 2 <= n; e += 2) {
            int j0 = s_j[w][e], j1 = s_j[w][e + 1];
            const float* K0 = Kbh + (long)j0 * DHh;
            const float* K1 = Kbh + (long)j1 * DHh;
            float p0 = q0 * K0[lane] + q1 * K0[lane + 32];
            float p1 = q0 * K1[lane] + q1 * K1[lane + 32];
#pragma unroll
            for (int off = 16; off; off >>= 1) {
                p0 += __shfl_xor_sync(0xffffffffu, p0, off);
                p1 += __shfl_xor_sync(0xffffffffu, p1, off);
            }
            if (lane == 0) { s_z[w][e] = p0; s_z[w][e + 1] = p1; }
        }
        if (e < n) {
            int j0 = s_j[w][e];
            const float* K0 = Kbh + (long)j0 * DHh;
            float p0 = q0 * K0[lane] + q1 * K0[lane + 32];
#pragma unroll
            for (int off = 16; off; off >>= 1)
                p0 += __shfl_xor_sync(0xffffffffu, p0, off);
            if (lane == 0) s_z[w][e] = p0;
        }
        __syncwarp();

        float tau = rmaxf[bhrow] - 1.02f;
        for (int it = 0; it < 48; ++it) {
            float s = 0.0f; int c = 0;
            for (int e2 = lane; e2 < n; e2 += 32) {
                float zz = s_z[w][e2];
                if (zz > tau) { s += zz; c++; }
            }
#pragma unroll
            for (int off = 16; off; off >>= 1) {
                s += __shfl_xor_sync(0xffffffffu, s, off);
                c += __shfl_xor_sync(0xffffffffu, c, off);
            }
            float nt2 = (s - 1.0f) / (float)c;
            if (nt2 == tau) break;
            tau = nt2;
        }
        if (lane == 0) { s_tau[w] = tau; s_cnt[w] = n; }

        float o0 = 0.0f, o1 = 0.0f;
        for (int e2 = 0; e2 < n; ++e2) {
            float p = s_z[w][e2] - tau;
            if (p > 0.0f) {
                const float* Vr = Vb + (long)s_j[w][e2] * DHh;
                o0 += p * Vr[lane];
                o1 += p * Vr[lane + 32];
            }
        }
        long hbase = (long)row * Dd + w * DHh;
        heads[hbase + lane] = o0;
        heads[hbase + lane + 32] = o1;
    } else {
        if (lane == 0) { s_over[w] = 1; s_cnt[w] = 0; s_tau[w] = 0.0f; }
    }

    __syncthreads();

    // deferred overflow heads: block-cooperative exact solve on shared z-row
    for (int h = 0; h < Hh; ++h) {
        if (!s_over[h]) continue;

        long bhrowH = ((long)b * Hh + h) * Ss + i;
        const float* QrowH = Q + bhrowH * DHh;
        const float* KbhH  = K + (((long)b * Hh + h) * Ss) * (long)DHh;
        float qh0 = QrowH[lane], qh1 = QrowH[lane + 32];

        block_zrow(KbhH, qh0, qh1, w, lane, s_zrow);
        __syncthreads();

        float tau = rmaxf[bhrowH] - 1.02f;
        for (int it = 0; it < 48; ++it) {
            float s = 0.0f; int c = 0;
#pragma unroll
            for (int k = 0; k < 8; ++k) {
                float zz = s_zrow[tid + k * 256];
                if (zz > tau) { s += zz; c++; }
            }
#pragma unroll
            for (int off = 16; off; off >>= 1) {
                s += __shfl_xor_sync(0xffffffffu, s, off);
                c += __shfl_xor_sync(0xffffffffu, c, off);
            }
            if (lane == 0) { s_part[w] = s; s_partc[w] = c; }
            __syncthreads();
            if (tid == 0) {
                float S = 0.0f; int C = 0;
#pragma unroll
                for (int k = 0; k < 8; ++k) { S += s_part[k]; C += s_partc[k]; }
                s_bcast = (S - 1.0f) / (float)C;
            }
            __syncthreads();
            float nt2 = s_bcast;
            bool done = (nt2 == tau);
            tau = nt2;
            __syncthreads();
            if (done) break;
        }
        if (tid == 0) s_tau[h] = tau;

        if (tid < DHh) {
            float o = 0.0f;
            for (int j = 0; j < Ss; ++j) {
                float p = s_zrow[j] - tau;
                if (p > 0.0f) o += p * Vb[(long)j * DHh + tid];
            }
            heads[(long)row * Dd + h * DHh + tid] = o;
        }

#pragma unroll
        for (int k = 0; k < 8; ++k) {
            float p = s_zrow[tid + k * 256] - tau;
            if (p > 0.0f) rv[k] += p;
        }
        __syncthreads();
    }

    // avg_attention: ownership scan over normal heads' candidate lists
#pragma unroll
    for (int h = 0; h < Hh; ++h) {
        int c = s_cnt[h];
        float th = s_tau[h];
        for (int e = 0; e < c; ++e) {
            int j = s_j[h][e];
            if ((j & 255) == tid) {
                float p = s_z[h][e] - th;
                if (p > 0.0f) rv[j >> 8] += p;
            }
        }
    }
    long abase = ((long)b * Ss + i) * (long)Ss;
#pragma unroll
    for (int k = 0; k < 8; ++k)
        avg_out[abase + tid + k * 256] = 0.125f * rv[k];
}

// ---------------------------------------------------------------------------
extern "C" void kernel_launch(void* const* d_in, const int* in_sizes, int n_in,
                              void* d_out, int out_size)
{
    const float* x    = (const float*)d_in[0];
    const float* Wq   = (const float*)d_in[1];
    const float* bq   = (const float*)d_in[2];
    const float* Wk   = (const float*)d_in[3];
    const float* bk   = (const float*)d_in[4];
    const float* Wv   = (const float*)d_in[5];
    const float* bv   = (const float*)d_in[6];
    const float* Wout = (const float*)d_in[7];
    const float* bout = (const float*)d_in[8];

    float* out   = (float*)d_out;
    float* x_out = out;                              // [B,S,D]
    float* avg   = out + (long)Bb * Ss * Dd;         // [B,S,S]

    float *Qp, *Kp, *Vp, *Hp, *Rp;
    unsigned short* Cp;
    int* Np;
    cudaGetSymbolAddress((void**)&Qp, g_Q);
    cudaGetSymbolAddress((void**)&Kp, g_K);
    cudaGetSymbolAddress((void**)&Vp, g_V);
    cudaGetSymbolAddress((void**)&Hp, g_heads);
    cudaGetSymbolAddress((void**)&Cp, g_cand);
    cudaGetSymbolAddress((void**)&Np, g_ccnt);
    cudaGetSymbolAddress((void**)&Rp, g_rmax);

    cudaFuncSetAttribute(qk_screen,
                         cudaFuncAttributeMaxDynamicSharedMemorySize, SCR_SMEM);
    cudaFuncSetAttribute(proj3t,
                         cudaFuncAttributeMaxDynamicSharedMemorySize, G3_SMEM);
    cudaFuncSetAttribute(wout3t,
                         cudaFuncAttributeMaxDynamicSharedMemorySize, G3_SMEM);

    // fused Q/K/V projections (3xtf32 tensor cores)
    proj3t<<<dim3(32, 17, 1), 256, G3_SMEM>>>(
        x, Wq, bq, Wk, bk, Wv, bv, Qp, Kp, Vp);

    // fused QK + two-pass candidate screening (final threshold)
    qk_screen<<<dim3(Ss / 128, 1, Bb * Hh), 256, SCR_SMEM>>>(
        Qp, Kp, Cp, Np, Rp);

    // exact sparsemax + heads + avg from candidate lists
    sparse_final<<<Bb * Ss, 256>>>(Cp, Np, Rp, Qp, Kp, Vp, Hp, avg);

    // x_out = heads @ Wout + bout (3xtf32 tensor cores)
    wout3t<<<dim3(32, 8, 1), 256, G3_SMEM>>>(Hp, Wout, bout, x_out);
}